// round 1
// baseline (speedup 1.0000x reference)
#include <cuda_runtime.h>
#include <cuda_bf16.h>

#define BSZ 64
#define NC  32

// Spatial sizes through the conv stack (stride 2, VALID, k=3)
// 255 -> 127 -> 63 -> 31 -> 15 -> 7
static const int H0 = 255, H1 = 127, H2 = 63, H3 = 31, H4 = 15, H5 = 7;

// ---------------- scratch (static device globals; no allocation) ----------------
__device__ float g_bufA[BSZ * NC * 127 * 127];   // conv1 out, conv3 out (reused)
__device__ float g_bufB[BSZ * NC * 63 * 63];     // conv2 out, conv4 out (reused)
__device__ float g_feat[BSZ * NC * 7 * 7];       // conv5 out == flattened features [64,1568]
__device__ float g_fc1[BSZ * 20];                // relu(l1) output
__device__ float g_coef[BSZ * 27];               // a[9], b[9], c[9] per batch

// ---------------- conv1: 3 -> 32, 255 -> 127, fused bias+relu+bn ----------------
__global__ void __launch_bounds__(128) conv1_kernel(
    const float* __restrict__ x, const float* __restrict__ w,
    const float* __restrict__ cbias,
    const float* __restrict__ bng, const float* __restrict__ bnb,
    const float* __restrict__ bnm, const float* __restrict__ bnv,
    float* __restrict__ out)
{
    __shared__ float ws[NC * 3 * 9];
    __shared__ float sc_s[NC], sh_s[NC], bias_s[NC];
    for (int i = threadIdx.x; i < NC * 3 * 9; i += blockDim.x) ws[i] = w[i];
    if (threadIdx.x < NC) {
        float sc = bng[threadIdx.x] * rsqrtf(bnv[threadIdx.x] + 1e-5f);
        sc_s[threadIdx.x]   = sc;
        sh_s[threadIdx.x]   = bnb[threadIdx.x] - bnm[threadIdx.x] * sc;
        bias_s[threadIdx.x] = cbias[threadIdx.x];
    }
    __syncthreads();

    const int HOUT = H1, HIN = H0;
    const int NXP = (HOUT + 1) / 2;   // 64
    int idx = blockIdx.x * blockDim.x + threadIdx.x;
    int total = BSZ * HOUT * NXP;
    if (idx >= total) return;
    int xp = idx % NXP;
    int t  = idx / NXP;
    int oy = t % HOUT;
    int b  = t / HOUT;
    int ox0 = 2 * xp;
    bool has1 = (ox0 + 1) < HOUT;

    float acc0[NC], acc1[NC];
#pragma unroll
    for (int oc = 0; oc < NC; ++oc) { acc0[oc] = 0.f; acc1[oc] = 0.f; }

    const float* xb = x + ((b * 3) * HIN + 2 * oy) * HIN + 2 * ox0;
#pragma unroll
    for (int ic = 0; ic < 3; ++ic) {
        const float* xc = xb + ic * HIN * HIN;
#pragma unroll
        for (int ky = 0; ky < 3; ++ky) {
            const float* row = xc + ky * HIN;
#pragma unroll
            for (int kx = 0; kx < 3; ++kx) {
                float x0 = row[kx];
                float x1 = has1 ? row[kx + 2] : 0.f;
                const float* wp = ws + ic * 9 + ky * 3 + kx;
#pragma unroll
                for (int oc = 0; oc < NC; ++oc) {
                    float wv = wp[oc * 3 * 9];
                    acc0[oc] = fmaf(x0, wv, acc0[oc]);
                    acc1[oc] = fmaf(x1, wv, acc1[oc]);
                }
            }
        }
    }

    int obase = ((b * NC) * HOUT + oy) * HOUT + ox0;
#pragma unroll
    for (int oc = 0; oc < NC; ++oc) {
        float y0 = fmaxf(acc0[oc] + bias_s[oc], 0.f) * sc_s[oc] + sh_s[oc];
        out[obase + oc * HOUT * HOUT] = y0;
        if (has1) {
            float y1 = fmaxf(acc1[oc] + bias_s[oc], 0.f) * sc_s[oc] + sh_s[oc];
            out[obase + oc * HOUT * HOUT + 1] = y1;
        }
    }
}

// ---------------- generic 32 -> 32 conv, stride 2, fused bias+relu+bn ----------------
template <int HIN, int HOUT>
__global__ void __launch_bounds__(128) convN_kernel(
    const float* __restrict__ x, const float* __restrict__ w,
    const float* __restrict__ cbias,
    const float* __restrict__ bng, const float* __restrict__ bnb,
    const float* __restrict__ bnm, const float* __restrict__ bnv,
    float* __restrict__ out)
{
    __shared__ float ws[NC * NC * 9];        // 36 KB
    __shared__ float sc_s[NC], sh_s[NC], bias_s[NC];
    for (int i = threadIdx.x; i < NC * NC * 9; i += blockDim.x) ws[i] = w[i];
    if (threadIdx.x < NC) {
        float sc = bng[threadIdx.x] * rsqrtf(bnv[threadIdx.x] + 1e-5f);
        sc_s[threadIdx.x]   = sc;
        sh_s[threadIdx.x]   = bnb[threadIdx.x] - bnm[threadIdx.x] * sc;
        bias_s[threadIdx.x] = cbias[threadIdx.x];
    }
    __syncthreads();

    constexpr int NXP = (HOUT + 1) / 2;
    int idx = blockIdx.x * blockDim.x + threadIdx.x;
    int total = BSZ * HOUT * NXP;
    if (idx >= total) return;
    int xp = idx % NXP;
    int t  = idx / NXP;
    int oy = t % HOUT;
    int b  = t / HOUT;
    int ox0 = 2 * xp;
    bool has1 = (ox0 + 1) < HOUT;

    float acc0[NC], acc1[NC];
#pragma unroll
    for (int oc = 0; oc < NC; ++oc) { acc0[oc] = 0.f; acc1[oc] = 0.f; }

    const float* xb = x + ((b * NC) * HIN + 2 * oy) * HIN + 2 * ox0;
    for (int ic = 0; ic < NC; ++ic) {
        const float* xc = xb + ic * HIN * HIN;
#pragma unroll
        for (int ky = 0; ky < 3; ++ky) {
            const float* row = xc + ky * HIN;
#pragma unroll
            for (int kx = 0; kx < 3; ++kx) {
                float x0 = row[kx];
                float x1 = has1 ? row[kx + 2] : 0.f;
                const float* wp = ws + ic * 9 + ky * 3 + kx;
#pragma unroll
                for (int oc = 0; oc < NC; ++oc) {
                    float wv = wp[oc * NC * 9];
                    acc0[oc] = fmaf(x0, wv, acc0[oc]);
                    acc1[oc] = fmaf(x1, wv, acc1[oc]);
                }
            }
        }
    }

    int obase = ((b * NC) * HOUT + oy) * HOUT + ox0;
#pragma unroll
    for (int oc = 0; oc < NC; ++oc) {
        float y0 = fmaxf(acc0[oc] + bias_s[oc], 0.f) * sc_s[oc] + sh_s[oc];
        out[obase + oc * HOUT * HOUT] = y0;
        if (has1) {
            float y1 = fmaxf(acc1[oc] + bias_s[oc], 0.f) * sc_s[oc] + sh_s[oc];
            out[obase + oc * HOUT * HOUT + 1] = y1;
        }
    }
}

// ---------------- FC1: [64,1568] @ [1568,20]^T + b, relu. One warp per output ----------------
__global__ void fc1_kernel(const float* __restrict__ feat, const float* __restrict__ w,
                           const float* __restrict__ bias, float* __restrict__ out)
{
    int gw   = (blockIdx.x * blockDim.x + threadIdx.x) >> 5;
    int lane = threadIdx.x & 31;
    if (gw >= BSZ * 20) return;
    int j = gw % 20, b = gw / 20;
    const float* f  = feat + b * 1568;
    const float* wr = w + j * 1568;
    float s = 0.f;
    for (int k = lane; k < 1568; k += 32) s = fmaf(f[k], wr[k], s);
#pragma unroll
    for (int o = 16; o; o >>= 1) s += __shfl_xor_sync(0xffffffffu, s, o);
    if (lane == 0) out[b * 20 + j] = fmaxf(s + bias[j], 0.f);
}

// ---------------- FC2 + natural-cubic-spline solve (Thomas) -> a,b,c coefficients ----------------
__global__ void spline_kernel(const float* __restrict__ fc1,
                              const float* __restrict__ l2w, const float* __restrict__ l2b,
                              float* __restrict__ coef)
{
    int b = blockIdx.x * blockDim.x + threadIdx.x;
    if (b >= BSZ) return;

    float ys[10];
#pragma unroll
    for (int k = 0; k < 10; ++k) {
        float s = l2b[k];
#pragma unroll
        for (int j = 0; j < 20; ++j) s = fmaf(fc1[b * 20 + j], l2w[k * 20 + j], s);
        ys[k] = s;
    }

    const float h = (float)(1.0 / 9.0);
    // rhs: d[i] = (6/h^2) * (ys[i] - 2 ys[i+1] + ys[i+2]),  i = 0..7
    const float c6h2 = 6.0f * 81.0f;
    float d[8];
#pragma unroll
    for (int i = 0; i < 8; ++i) d[i] = c6h2 * (ys[i] - 2.f * ys[i + 1] + ys[i + 2]);

    // Thomas solve: tridiag(1,4,1) * M[1..8] = d
    float cp[8], dp[8];
    cp[0] = 0.25f; dp[0] = d[0] * 0.25f;
#pragma unroll
    for (int i = 1; i < 8; ++i) {
        float mden = 4.f - cp[i - 1];
        cp[i] = 1.f / mden;
        dp[i] = (d[i] - dp[i - 1]) / mden;
    }
    float M[10];
    M[0] = 0.f; M[9] = 0.f;
    M[8] = dp[7];
#pragma unroll
    for (int i = 6; i >= 0; --i) M[i + 1] = dp[i] - cp[i] * M[i + 2];

#pragma unroll
    for (int i = 0; i < 9; ++i) {
        coef[b * 27 + i]      = (M[i + 1] - M[i]) / (6.f * h);
        coef[b * 27 + 9 + i]  = M[i] * 0.5f;
        coef[b * 27 + 18 + i] = (ys[i + 1] - ys[i]) / h - (M[i + 1] + 2.f * M[i]) * (h / 6.f);
    }
}

// ---------------- final fused bucketize + gather + cubic eval ----------------
__global__ void eval_kernel(const float* __restrict__ x, const float* __restrict__ coef,
                            float* __restrict__ out, int n)
{
    int idx = blockIdx.x * blockDim.x + threadIdx.x;
    if (idx >= n) return;
    const int per = 3 * 255 * 255;
    int b = idx / per;
    float xv = x[idx];
    const float h = (float)(1.0 / 9.0);
    float q = xv / h;                       // match reference: divide, clip, floor
    q = fminf(fmaxf(q, 0.f), 8.f);
    int xi = (int)floorf(q);
    float xf = xv - (float)xi * h;
    const float* cf = coef + b * 27;
    float a  = __ldg(cf + xi);
    float bb = __ldg(cf + 9 + xi);
    float cc = __ldg(cf + 18 + xi);
    out[idx] = ((a * xf + bb) * xf + cc) * xf;
}

// ---------------- launch ----------------
extern "C" void kernel_launch(void* const* d_in, const int* in_sizes, int n_in,
                              void* d_out, int out_size)
{
    const float* batch = (const float*)d_in[0];   // [64,3,255,255]
    const float* c1_w  = (const float*)d_in[1];   // [32,3,3,3]
    const float* c1_b  = (const float*)d_in[2];   // [32]
    const float* cw    = (const float*)d_in[3];   // [4,32,32,3,3]
    const float* cb    = (const float*)d_in[4];   // [4,32]
    const float* bn_g  = (const float*)d_in[5];   // [5,32]
    const float* bn_b  = (const float*)d_in[6];
    const float* bn_m  = (const float*)d_in[7];
    const float* bn_v  = (const float*)d_in[8];
    const float* l1_w  = (const float*)d_in[9];   // [20,1568]
    const float* l1_b  = (const float*)d_in[10];  // [20]
    const float* l2_w  = (const float*)d_in[11];  // [10,20]
    const float* l2_b  = (const float*)d_in[12];  // [10]
    float* out = (float*)d_out;

    float* bufA; cudaGetSymbolAddress((void**)&bufA, g_bufA);
    float* bufB; cudaGetSymbolAddress((void**)&bufB, g_bufB);
    float* feat; cudaGetSymbolAddress((void**)&feat, g_feat);
    float* fc1;  cudaGetSymbolAddress((void**)&fc1,  g_fc1);
    float* coef; cudaGetSymbolAddress((void**)&coef, g_coef);

    const int TB = 128;

    // conv1: 255 -> 127
    {
        int total = BSZ * H1 * ((H1 + 1) / 2);
        conv1_kernel<<<(total + TB - 1) / TB, TB>>>(
            batch, c1_w, c1_b, bn_g + 0 * NC, bn_b + 0 * NC, bn_m + 0 * NC, bn_v + 0 * NC, bufA);
    }
    // conv2: 127 -> 63
    {
        int total = BSZ * H2 * ((H2 + 1) / 2);
        convN_kernel<H1, H2><<<(total + TB - 1) / TB, TB>>>(
            bufA, cw + 0 * NC * NC * 9, cb + 0 * NC,
            bn_g + 1 * NC, bn_b + 1 * NC, bn_m + 1 * NC, bn_v + 1 * NC, bufB);
    }
    // conv3: 63 -> 31
    {
        int total = BSZ * H3 * ((H3 + 1) / 2);
        convN_kernel<H2, H3><<<(total + TB - 1) / TB, TB>>>(
            bufB, cw + 1 * NC * NC * 9, cb + 1 * NC,
            bn_g + 2 * NC, bn_b + 2 * NC, bn_m + 2 * NC, bn_v + 2 * NC, bufA);
    }
    // conv4: 31 -> 15
    {
        int total = BSZ * H4 * ((H4 + 1) / 2);
        convN_kernel<H3, H4><<<(total + TB - 1) / TB, TB>>>(
            bufA, cw + 2 * NC * NC * 9, cb + 2 * NC,
            bn_g + 3 * NC, bn_b + 3 * NC, bn_m + 3 * NC, bn_v + 3 * NC, bufB);
    }
    // conv5: 15 -> 7  (output is the flattened feature [64, 1568] in NCHW order)
    {
        int total = BSZ * H5 * ((H5 + 1) / 2);
        convN_kernel<H4, H5><<<(total + TB - 1) / TB, TB>>>(
            bufB, cw + 3 * NC * NC * 9, cb + 3 * NC,
            bn_g + 4 * NC, bn_b + 4 * NC, bn_m + 4 * NC, bn_v + 4 * NC, feat);
    }
    // FC1 (warp per output scalar)
    {
        int warps = BSZ * 20;
        int threads = warps * 32;
        fc1_kernel<<<(threads + 255) / 256, 256>>>(feat, l1_w, l1_b, fc1);
    }
    // FC2 + spline coefficient solve
    spline_kernel<<<1, BSZ>>>(fc1, l2_w, l2_b, coef);

    // Final fused bucketize + cubic eval over all pixels
    {
        int n = out_size;   // 64*3*255*255
        eval_kernel<<<(n + 255) / 256, 256>>>(batch, coef, out, n);
    }
}

// round 2
// speedup vs baseline: 1.0751x; 1.0751x over previous
#include <cuda_runtime.h>
#include <cuda_bf16.h>

#define BSZ 64
#define NC  32

// Spatial sizes through the conv stack (stride 2, VALID, k=3)
// 255 -> 127 -> 63 -> 31 -> 15 -> 7
static const int H0 = 255, H1 = 127, H2 = 63, H3 = 31, H4 = 15, H5 = 7;

// ---------------- scratch (static device globals; no allocation) ----------------
__device__ float g_bufA[BSZ * NC * 127 * 127];   // conv1 out, conv3 out (reused)
__device__ float g_bufB[BSZ * NC * 63 * 63];     // conv2 out, conv4 out (reused)
__device__ float g_feat[BSZ * NC * 7 * 7];       // conv5 out == flattened features [64,1568]
__device__ float g_fc1[BSZ * 20];                // relu(l1) output
__device__ float g_coef[BSZ * 27];               // a[9], b[9], c[9] per batch

// ---------------- conv1: 3 -> 32, 255 -> 127, fused bias+relu+bn ----------------
__global__ void __launch_bounds__(128) conv1_kernel(
    const float* __restrict__ x, const float* __restrict__ w,
    const float* __restrict__ cbias,
    const float* __restrict__ bng, const float* __restrict__ bnb,
    const float* __restrict__ bnm, const float* __restrict__ bnv,
    float* __restrict__ out)
{
    __shared__ float ws[NC * 3 * 9];
    __shared__ float sc_s[NC], sh_s[NC], bias_s[NC];
    for (int i = threadIdx.x; i < NC * 3 * 9; i += blockDim.x) ws[i] = w[i];
    if (threadIdx.x < NC) {
        float sc = bng[threadIdx.x] * rsqrtf(bnv[threadIdx.x] + 1e-5f);
        sc_s[threadIdx.x]   = sc;
        sh_s[threadIdx.x]   = bnb[threadIdx.x] - bnm[threadIdx.x] * sc;
        bias_s[threadIdx.x] = cbias[threadIdx.x];
    }
    __syncthreads();

    const int HOUT = H1, HIN = H0;
    const int NXP = (HOUT + 1) / 2;   // 64
    int idx = blockIdx.x * blockDim.x + threadIdx.x;
    int total = BSZ * HOUT * NXP;
    if (idx >= total) return;
    int xp = idx % NXP;
    int t  = idx / NXP;
    int oy = t % HOUT;
    int b  = t / HOUT;
    int ox0 = 2 * xp;
    bool has1 = (ox0 + 1) < HOUT;

    float acc0[NC], acc1[NC];
#pragma unroll
    for (int oc = 0; oc < NC; ++oc) { acc0[oc] = 0.f; acc1[oc] = 0.f; }

    const float* xb = x + ((b * 3) * HIN + 2 * oy) * HIN + 2 * ox0;
#pragma unroll
    for (int ic = 0; ic < 3; ++ic) {
        const float* xc = xb + ic * HIN * HIN;
#pragma unroll
        for (int ky = 0; ky < 3; ++ky) {
            const float* row = xc + ky * HIN;
#pragma unroll
            for (int kx = 0; kx < 3; ++kx) {
                float x0 = row[kx];
                float x1 = has1 ? row[kx + 2] : 0.f;
                const float* wp = ws + ic * 9 + ky * 3 + kx;
#pragma unroll
                for (int oc = 0; oc < NC; ++oc) {
                    float wv = wp[oc * 3 * 9];
                    acc0[oc] = fmaf(x0, wv, acc0[oc]);
                    acc1[oc] = fmaf(x1, wv, acc1[oc]);
                }
            }
        }
    }

    int obase = ((b * NC) * HOUT + oy) * HOUT + ox0;
#pragma unroll
    for (int oc = 0; oc < NC; ++oc) {
        float y0 = fmaxf(acc0[oc] + bias_s[oc], 0.f) * sc_s[oc] + sh_s[oc];
        out[obase + oc * HOUT * HOUT] = y0;
        if (has1) {
            float y1 = fmaxf(acc1[oc] + bias_s[oc], 0.f) * sc_s[oc] + sh_s[oc];
            out[obase + oc * HOUT * HOUT + 1] = y1;
        }
    }
}

// ---------------- generic 32 -> 32 conv, stride 2, fused bias+relu+bn ----------------
// OCG = output channels per thread. Threads: BSZ * HOUT * NXP * (NC/OCG).
// Layout: xp fastest (coalesced input rows), then ocg group, then oy, then b.
template <int HIN, int HOUT, int OCG>
__global__ void __launch_bounds__(128) convN_kernel(
    const float* __restrict__ x, const float* __restrict__ w,
    const float* __restrict__ cbias,
    const float* __restrict__ bng, const float* __restrict__ bnb,
    const float* __restrict__ bnm, const float* __restrict__ bnv,
    float* __restrict__ out)
{
    __shared__ float ws[NC * NC * 9];        // 36 KB, all output channels
    __shared__ float sc_s[NC], sh_s[NC], bias_s[NC];
    for (int i = threadIdx.x; i < NC * NC * 9; i += blockDim.x) ws[i] = w[i];
    if (threadIdx.x < NC) {
        float sc = bng[threadIdx.x] * rsqrtf(bnv[threadIdx.x] + 1e-5f);
        sc_s[threadIdx.x]   = sc;
        sh_s[threadIdx.x]   = bnb[threadIdx.x] - bnm[threadIdx.x] * sc;
        bias_s[threadIdx.x] = cbias[threadIdx.x];
    }
    __syncthreads();

    constexpr int NXP   = (HOUT + 1) / 2;
    constexpr int NGRP  = NC / OCG;
    int idx = blockIdx.x * blockDim.x + threadIdx.x;
    int total = BSZ * HOUT * NXP * NGRP;
    if (idx >= total) return;
    int xp = idx % NXP;
    int t  = idx / NXP;
    int g  = t % NGRP;     // output-channel group
    t /= NGRP;
    int oy = t % HOUT;
    int b  = t / HOUT;
    int ox0 = 2 * xp;
    bool has1 = (ox0 + 1) < HOUT;
    int oc0 = g * OCG;

    float acc0[OCG], acc1[OCG];
#pragma unroll
    for (int oc = 0; oc < OCG; ++oc) { acc0[oc] = 0.f; acc1[oc] = 0.f; }

    const float* xb = x + ((b * NC) * HIN + 2 * oy) * HIN + 2 * ox0;
    for (int ic = 0; ic < NC; ++ic) {
        const float* xc = xb + ic * HIN * HIN;
#pragma unroll
        for (int ky = 0; ky < 3; ++ky) {
            const float* row = xc + ky * HIN;
#pragma unroll
            for (int kx = 0; kx < 3; ++kx) {
                float x0 = row[kx];
                float x1 = has1 ? row[kx + 2] : 0.f;
                const float* wp = ws + oc0 * NC * 9 + ic * 9 + ky * 3 + kx;
#pragma unroll
                for (int oc = 0; oc < OCG; ++oc) {
                    float wv = wp[oc * NC * 9];
                    acc0[oc] = fmaf(x0, wv, acc0[oc]);
                    acc1[oc] = fmaf(x1, wv, acc1[oc]);
                }
            }
        }
    }

    int obase = ((b * NC + oc0) * HOUT + oy) * HOUT + ox0;
#pragma unroll
    for (int oc = 0; oc < OCG; ++oc) {
        float y0 = fmaxf(acc0[oc] + bias_s[oc0 + oc], 0.f) * sc_s[oc0 + oc] + sh_s[oc0 + oc];
        out[obase + oc * HOUT * HOUT] = y0;
        if (has1) {
            float y1 = fmaxf(acc1[oc] + bias_s[oc0 + oc], 0.f) * sc_s[oc0 + oc] + sh_s[oc0 + oc];
            out[obase + oc * HOUT * HOUT + 1] = y1;
        }
    }
}

// ---------------- FC1: [64,1568] @ [1568,20]^T + b, relu. One warp per output ----------------
__global__ void fc1_kernel(const float* __restrict__ feat, const float* __restrict__ w,
                           const float* __restrict__ bias, float* __restrict__ out)
{
    int gw   = (blockIdx.x * blockDim.x + threadIdx.x) >> 5;
    int lane = threadIdx.x & 31;
    if (gw >= BSZ * 20) return;
    int j = gw % 20, b = gw / 20;
    const float* f  = feat + b * 1568;
    const float* wr = w + j * 1568;
    float s = 0.f;
    for (int k = lane; k < 1568; k += 32) s = fmaf(f[k], wr[k], s);
#pragma unroll
    for (int o = 16; o; o >>= 1) s += __shfl_xor_sync(0xffffffffu, s, o);
    if (lane == 0) out[b * 20 + j] = fmaxf(s + bias[j], 0.f);
}

// ---------------- FC2 + natural-cubic-spline solve (Thomas) -> a,b,c coefficients ----------------
__global__ void spline_kernel(const float* __restrict__ fc1,
                              const float* __restrict__ l2w, const float* __restrict__ l2b,
                              float* __restrict__ coef)
{
    int b = blockIdx.x * blockDim.x + threadIdx.x;
    if (b >= BSZ) return;

    float ys[10];
#pragma unroll
    for (int k = 0; k < 10; ++k) {
        float s = l2b[k];
#pragma unroll
        for (int j = 0; j < 20; ++j) s = fmaf(fc1[b * 20 + j], l2w[k * 20 + j], s);
        ys[k] = s;
    }

    const float h = (float)(1.0 / 9.0);
    const float c6h2 = 6.0f * 81.0f;
    float d[8];
#pragma unroll
    for (int i = 0; i < 8; ++i) d[i] = c6h2 * (ys[i] - 2.f * ys[i + 1] + ys[i + 2]);

    // Thomas solve: tridiag(1,4,1) * M[1..8] = d
    float cp[8], dp[8];
    cp[0] = 0.25f; dp[0] = d[0] * 0.25f;
#pragma unroll
    for (int i = 1; i < 8; ++i) {
        float mden = 4.f - cp[i - 1];
        cp[i] = 1.f / mden;
        dp[i] = (d[i] - dp[i - 1]) / mden;
    }
    float M[10];
    M[0] = 0.f; M[9] = 0.f;
    M[8] = dp[7];
#pragma unroll
    for (int i = 6; i >= 0; --i) M[i + 1] = dp[i] - cp[i] * M[i + 2];

#pragma unroll
    for (int i = 0; i < 9; ++i) {
        coef[b * 27 + i]      = (M[i + 1] - M[i]) / (6.f * h);
        coef[b * 27 + 9 + i]  = M[i] * 0.5f;
        coef[b * 27 + 18 + i] = (ys[i + 1] - ys[i]) / h - (M[i + 1] + 2.f * M[i]) * (h / 6.f);
    }
}

// ---------------- final fused bucketize + gather + cubic eval (float4) ----------------
__global__ void eval_kernel(const float4* __restrict__ x, const float* __restrict__ coef,
                            float4* __restrict__ out, int n4)
{
    int idx = blockIdx.x * blockDim.x + threadIdx.x;
    if (idx >= n4) return;
    const int per = 3 * 255 * 255;            // 195075 (odd -> batch can change mid-vector)
    int i0 = idx * 4;
    int b0 = i0 / per;
    int r0 = i0 - b0 * per;

    float4 xv = x[idx];
    float vals[4] = {xv.x, xv.y, xv.z, xv.w};
    float res[4];
    const float h    = (float)(1.0 / 9.0);
    const float invh = 9.0f;
#pragma unroll
    for (int j = 0; j < 4; ++j) {
        int b = b0 + ((r0 + j) >= per ? 1 : 0);
        float v = vals[j];
        float q = v * invh;                   // == v / h for h = 1/9 exactly representable? use div-consistent clamp
        q = fminf(fmaxf(v / h, 0.f), 8.f);
        int xi = (int)floorf(q);
        float xf = v - (float)xi * h;
        const float* cf = coef + b * 27;
        float a  = __ldg(cf + xi);
        float bb = __ldg(cf + 9 + xi);
        float cc = __ldg(cf + 18 + xi);
        res[j] = ((a * xf + bb) * xf + cc) * xf;
        (void)q;
    }
    out[idx] = make_float4(res[0], res[1], res[2], res[3]);
}

// ---------------- launch ----------------
extern "C" void kernel_launch(void* const* d_in, const int* in_sizes, int n_in,
                              void* d_out, int out_size)
{
    const float* batch = (const float*)d_in[0];   // [64,3,255,255]
    const float* c1_w  = (const float*)d_in[1];   // [32,3,3,3]
    const float* c1_b  = (const float*)d_in[2];   // [32]
    const float* cw    = (const float*)d_in[3];   // [4,32,32,3,3]
    const float* cb    = (const float*)d_in[4];   // [4,32]
    const float* bn_g  = (const float*)d_in[5];   // [5,32]
    const float* bn_b  = (const float*)d_in[6];
    const float* bn_m  = (const float*)d_in[7];
    const float* bn_v  = (const float*)d_in[8];
    const float* l1_w  = (const float*)d_in[9];   // [20,1568]
    const float* l1_b  = (const float*)d_in[10];  // [20]
    const float* l2_w  = (const float*)d_in[11];  // [10,20]
    const float* l2_b  = (const float*)d_in[12];  // [10]
    float* out = (float*)d_out;

    float* bufA; cudaGetSymbolAddress((void**)&bufA, g_bufA);
    float* bufB; cudaGetSymbolAddress((void**)&bufB, g_bufB);
    float* feat; cudaGetSymbolAddress((void**)&feat, g_feat);
    float* fc1;  cudaGetSymbolAddress((void**)&fc1,  g_fc1);
    float* coef; cudaGetSymbolAddress((void**)&coef, g_coef);

    const int TB = 128;

    // conv1: 255 -> 127
    {
        int total = BSZ * H1 * ((H1 + 1) / 2);
        conv1_kernel<<<(total + TB - 1) / TB, TB>>>(
            batch, c1_w, c1_b, bn_g + 0 * NC, bn_b + 0 * NC, bn_m + 0 * NC, bn_v + 0 * NC, bufA);
    }
    // conv2: 127 -> 63  (OCG=32: input is 132MB, avoid re-reads)
    {
        int total = BSZ * H2 * ((H2 + 1) / 2) * (NC / 32);
        convN_kernel<H1, H2, 32><<<(total + TB - 1) / TB, TB>>>(
            bufA, cw + 0 * NC * NC * 9, cb + 0 * NC,
            bn_g + 1 * NC, bn_b + 1 * NC, bn_m + 1 * NC, bn_v + 1 * NC, bufB);
    }
    // conv3: 63 -> 31  (OCG=8: 4x parallelism, 32MB input hits L2 on re-reads)
    {
        int total = BSZ * H3 * ((H3 + 1) / 2) * (NC / 8);
        convN_kernel<H2, H3, 8><<<(total + TB - 1) / TB, TB>>>(
            bufB, cw + 1 * NC * NC * 9, cb + 1 * NC,
            bn_g + 2 * NC, bn_b + 2 * NC, bn_m + 2 * NC, bn_v + 2 * NC, bufA);
    }
    // conv4: 31 -> 15  (OCG=8: 240 blocks instead of 60)
    {
        int total = BSZ * H4 * ((H4 + 1) / 2) * (NC / 8);
        convN_kernel<H3, H4, 8><<<(total + TB - 1) / TB, TB>>>(
            bufA, cw + 2 * NC * NC * 9, cb + 2 * NC,
            bn_g + 3 * NC, bn_b + 3 * NC, bn_m + 3 * NC, bn_v + 3 * NC, bufB);
    }
    // conv5: 15 -> 7  (OCG=4: 112 blocks instead of 14)
    {
        int total = BSZ * H5 * ((H5 + 1) / 2) * (NC / 4);
        convN_kernel<H4, H5, 4><<<(total + TB - 1) / TB, TB>>>(
            bufB, cw + 3 * NC * NC * 9, cb + 3 * NC,
            bn_g + 4 * NC, bn_b + 4 * NC, bn_m + 4 * NC, bn_v + 4 * NC, feat);
    }
    // FC1 (warp per output scalar)
    {
        int warps = BSZ * 20;
        int threads = warps * 32;
        fc1_kernel<<<(threads + 255) / 256, 256>>>(feat, l1_w, l1_b, fc1);
    }
    // FC2 + spline coefficient solve
    spline_kernel<<<1, BSZ>>>(fc1, l2_w, l2_b, coef);

    // Final fused bucketize + cubic eval over all pixels
    {
        int n4 = out_size / 4;   // 12,484,800 / 4
        eval_kernel<<<(n4 + 255) / 256, 256>>>((const float4*)batch, coef, (float4*)out, n4);
    }
}